// round 6
// baseline (speedup 1.0000x reference)
#include <cuda_runtime.h>

// Problem dims (fixed per reference)
#define TT 512
#define BB 64
#define II 768
#define DD 2048
#define LEAK 0.5f

// Stage-2 persistent-kernel config
#define S2_NCTA 128           // <= 148 SMs -> all CTAs co-resident (persistent)
#define S2_DTILE 16           // DD / S2_NCTA
#define S2_KT 64              // k-chunk

// Scratch: double-buffered hidden state + per-step barrier counters.
// (No allocations allowed -> __device__ globals.)
__device__ float g_h[2][BB * DD];
__device__ unsigned int g_bar[TT];

// ---------------------------------------------------------------------------
// Init: zero h0 and barrier counters (must run every replay for determinism)
// ---------------------------------------------------------------------------
__global__ void init_kernel() {
    int idx = blockIdx.x * blockDim.x + threadIdx.x;
    int stride = gridDim.x * blockDim.x;
    float* h = (float*)g_h;
    for (int i = idx; i < 2 * BB * DD; i += stride) h[i] = 0.0f;
    for (int i = idx; i < TT; i += stride) g_bar[i] = 0u;
}

// ---------------------------------------------------------------------------
// Stage 1: proj[t,b,n] = sum_k batch[t,b,k] * W_in[n,k] + bias[n]
// A = batch flattened [M=TT*BB, II] row-major; W = [DD, II] row-major.
// Result scattered straight into out[b, t, n] (overwritten later by h).
// Tiling: 64x64 CTA tile, 16-wide K tile, 256 threads, 4x4 micro-tile.
// ---------------------------------------------------------------------------
__global__ __launch_bounds__(256) void proj_kernel(
    const float* __restrict__ A,
    const float* __restrict__ W,
    const float* __restrict__ bias,
    float* __restrict__ out)
{
    __shared__ __align__(16) float As[16][68];   // [k][m], padded (68*4B = 17*16B)
    __shared__ __align__(16) float Bs[16][68];   // [k][n]

    const int m0 = blockIdx.y * 64;
    const int n0 = blockIdx.x * 64;
    const int tid = threadIdx.x;
    const int tx = tid & 15;    // n micro-group
    const int ty = tid >> 4;    // m micro-group

    // loader coords (4 elements per thread per tile, 64 rows x 16 k)
    int lr[4], lc[4];
#pragma unroll
    for (int i = 0; i < 4; i++) {
        int idx = tid + i * 256;
        lr[i] = idx >> 4;
        lc[i] = idx & 15;
    }

    float acc[4][4];
#pragma unroll
    for (int i = 0; i < 4; i++)
#pragma unroll
        for (int j = 0; j < 4; j++) acc[i][j] = 0.0f;

    // preload first k-tile into registers
    float a_reg[4], b_reg[4];
#pragma unroll
    for (int i = 0; i < 4; i++) {
        a_reg[i] = A[(size_t)(m0 + lr[i]) * II + lc[i]];
        b_reg[i] = W[(size_t)(n0 + lr[i]) * II + lc[i]];
    }

    for (int kt = 0; kt < II; kt += 16) {
#pragma unroll
        for (int i = 0; i < 4; i++) {
            As[lc[i]][lr[i]] = a_reg[i];
            Bs[lc[i]][lr[i]] = b_reg[i];
        }
        __syncthreads();

        if (kt + 16 < II) {
#pragma unroll
            for (int i = 0; i < 4; i++) {
                a_reg[i] = A[(size_t)(m0 + lr[i]) * II + (kt + 16) + lc[i]];
                b_reg[i] = W[(size_t)(n0 + lr[i]) * II + (kt + 16) + lc[i]];
            }
        }

#pragma unroll
        for (int k = 0; k < 16; k++) {
            float4 a4 = *(const float4*)&As[k][ty * 4];
            float4 b4 = *(const float4*)&Bs[k][tx * 4];
            float av[4] = {a4.x, a4.y, a4.z, a4.w};
            float bv[4] = {b4.x, b4.y, b4.z, b4.w};
#pragma unroll
            for (int i = 0; i < 4; i++)
#pragma unroll
                for (int j = 0; j < 4; j++)
                    acc[i][j] += av[i] * bv[j];
        }
        __syncthreads();
    }

    // scatter: m = t*BB + b ; m0 is a multiple of 64 == BB, so t is constant/CTA
    const int t = m0 / BB;
#pragma unroll
    for (int i = 0; i < 4; i++) {
        int b = ty * 4 + i;
        size_t base = (size_t)b * (TT * DD) + (size_t)t * DD;
#pragma unroll
        for (int j = 0; j < 4; j++) {
            int n = n0 + tx * 4 + j;
            out[base + n] = acc[i][j] + bias[n];
        }
    }
}

// ---------------------------------------------------------------------------
// Stage 2: persistent recurrence kernel.
// h_t = 0.5*h_{t-1} + 0.5*tanh(proj_t + h_{t-1} @ W_res^T)
// 128 CTAs; CTA c owns d-columns [16c, 16c+16) x all 64 batch rows.
// Grid barrier per step via per-step counters (zeroed by init each replay).
// proj_t read from out[b,t,d] then overwritten in-place with h_t.
// ---------------------------------------------------------------------------
__device__ __forceinline__ float fast_tanh(float x) {
    // 1 - 2/(e^{2x}+1): exact +/-1 at saturation (e^inf -> inf, e^-inf -> 0)
    float e = __expf(2.0f * x);
    return 1.0f - 2.0f / (e + 1.0f);
}

__global__ __launch_bounds__(256) void recur_kernel(
    const float* __restrict__ Wr,   // [DD, DD] row-major
    float* __restrict__ out)        // [BB, TT, DD]: holds proj, rewritten to h
{
    __shared__ float Hs[BB][S2_KT + 1];         // [b][k] 64x65 (conflict-free)
    __shared__ float Ws[S2_KT][S2_DTILE + 1];   // [k][d] 64x17

    const int tid = threadIdx.x;
    const int dd = tid & 15;        // d within tile
    const int bq = tid >> 4;        // batch quad 0..15
    const int d0 = blockIdx.x * S2_DTILE;
    const int d  = d0 + dd;

    // loader coords
    int hb[16], hk[16];
#pragma unroll
    for (int i = 0; i < 16; i++) {
        int idx = tid + i * 256;
        hb[i] = idx >> 6;           // 0..63
        hk[i] = idx & 63;
    }
    int wd[4], wk[4];
#pragma unroll
    for (int i = 0; i < 4; i++) {
        int idx = tid + i * 256;
        wd[i] = idx >> 6;           // 0..15
        wk[i] = idx & 63;
    }

    for (int t = 0; t < TT; t++) {
        const float* hin = g_h[t & 1];
        float* hout = g_h[(t + 1) & 1];

        float acc[4] = {0.0f, 0.0f, 0.0f, 0.0f};

        // prefetch chunk 0
        float h_reg[16], w_reg[4];
#pragma unroll
        for (int i = 0; i < 16; i++)
            h_reg[i] = __ldcg(&hin[hb[i] * DD + hk[i]]);
#pragma unroll
        for (int i = 0; i < 4; i++)
            w_reg[i] = Wr[(size_t)(d0 + wd[i]) * DD + wk[i]];

        for (int k0 = 0; k0 < DD; k0 += S2_KT) {
#pragma unroll
            for (int i = 0; i < 16; i++) Hs[hb[i]][hk[i]] = h_reg[i];
#pragma unroll
            for (int i = 0; i < 4; i++) Ws[wk[i]][wd[i]] = w_reg[i];
            __syncthreads();

            if (k0 + S2_KT < DD) {
                int kn = k0 + S2_KT;
#pragma unroll
                for (int i = 0; i < 16; i++)
                    h_reg[i] = __ldcg(&hin[hb[i] * DD + kn + hk[i]]);
#pragma unroll
                for (int i = 0; i < 4; i++)
                    w_reg[i] = Wr[(size_t)(d0 + wd[i]) * DD + kn + wk[i]];
            }

#pragma unroll
            for (int k = 0; k < S2_KT; k++) {
                float w = Ws[k][dd];
                acc[0] += Hs[bq * 4 + 0][k] * w;
                acc[1] += Hs[bq * 4 + 1][k] * w;
                acc[2] += Hs[bq * 4 + 2][k] * w;
                acc[3] += Hs[bq * 4 + 3][k] * w;
            }
            __syncthreads();
        }

        // epilogue: x = proj + hW ; h_new = 0.5 h + 0.5 tanh(x)
#pragma unroll
        for (int i = 0; i < 4; i++) {
            int b = bq * 4 + i;
            size_t oidx = (size_t)b * (TT * DD) + (size_t)t * DD + d;
            float x = out[oidx] + acc[i];
            float th = fast_tanh(x);
            float hprev = __ldcg(&hin[b * DD + d]);
            float hn = (1.0f - LEAK) * hprev + LEAK * th;
            hout[b * DD + d] = hn;
            out[oidx] = hn;
        }

        // grid-wide barrier (skip after the final step)
        if (t < TT - 1) {
            __threadfence();            // release: every thread's stores
            __syncthreads();
            if (tid == 0) {
                atomicAdd(&g_bar[t], 1u);
                volatile unsigned int* p = &g_bar[t];
                while (*p < (unsigned)S2_NCTA) { __nanosleep(64); }
            }
            __syncthreads();
        }
    }
}

// ---------------------------------------------------------------------------
// Launch
// ---------------------------------------------------------------------------
extern "C" void kernel_launch(void* const* d_in, const int* in_sizes, int n_in,
                              void* d_out, int out_size) {
    (void)in_sizes; (void)n_in; (void)out_size;
    const float* batch   = (const float*)d_in[0];  // [TT, BB, II]
    const float* input_w = (const float*)d_in[1];  // [DD, II]
    const float* res_w   = (const float*)d_in[2];  // [DD, DD]
    const float* bias    = (const float*)d_in[3];  // [DD]
    float* out = (float*)d_out;                    // [BB, TT, DD]

    init_kernel<<<64, 256>>>();

    dim3 g1(DD / 64, (TT * BB) / 64);   // 32 x 512
    proj_kernel<<<g1, 256>>>(batch, input_w, bias, out);

    recur_kernel<<<S2_NCTA, 256>>>(res_w, out);
}

// round 7
// speedup vs baseline: 1.0006x; 1.0006x over previous
#include <cuda_runtime.h>

// Problem dims (fixed per reference)
#define TT 512
#define BB 64
#define II 768
#define DD 2048
#define LEAK 0.5f

// Stage-2 persistent-kernel config
#define S2_NCTA 128           // <= 148 SMs -> all CTAs co-resident (persistent)
#define S2_DTILE 16           // DD / S2_NCTA
#define S2_KT 64              // k-chunk

// Scratch: double-buffered hidden state + per-step barrier counters.
// (No allocations allowed -> __device__ globals.)
__device__ float g_h[2][BB * DD];
__device__ unsigned int g_bar[TT];

// ---------------------------------------------------------------------------
// Init: zero h0 and barrier counters (must run every replay for determinism)
// ---------------------------------------------------------------------------
__global__ void init_kernel() {
    int idx = blockIdx.x * blockDim.x + threadIdx.x;
    int stride = gridDim.x * blockDim.x;
    float* h = (float*)g_h;
    for (int i = idx; i < 2 * BB * DD; i += stride) h[i] = 0.0f;
    for (int i = idx; i < TT; i += stride) g_bar[i] = 0u;
}

// ---------------------------------------------------------------------------
// Stage 1: proj[t,b,n] = sum_k batch[t,b,k] * W_in[n,k] + bias[n]
// A = batch flattened [M=TT*BB, II] row-major; W = [DD, II] row-major.
// Result scattered straight into out[b, t, n] (overwritten later by h).
// Tiling: 64x64 CTA tile, 16-wide K tile, 256 threads, 4x4 micro-tile.
// ---------------------------------------------------------------------------
__global__ __launch_bounds__(256) void proj_kernel(
    const float* __restrict__ A,
    const float* __restrict__ W,
    const float* __restrict__ bias,
    float* __restrict__ out)
{
    __shared__ __align__(16) float As[16][68];   // [k][m], padded (68*4B = 17*16B)
    __shared__ __align__(16) float Bs[16][68];   // [k][n]

    const int m0 = blockIdx.y * 64;
    const int n0 = blockIdx.x * 64;
    const int tid = threadIdx.x;
    const int tx = tid & 15;    // n micro-group
    const int ty = tid >> 4;    // m micro-group

    // loader coords (4 elements per thread per tile, 64 rows x 16 k)
    int lr[4], lc[4];
#pragma unroll
    for (int i = 0; i < 4; i++) {
        int idx = tid + i * 256;
        lr[i] = idx >> 4;
        lc[i] = idx & 15;
    }

    float acc[4][4];
#pragma unroll
    for (int i = 0; i < 4; i++)
#pragma unroll
        for (int j = 0; j < 4; j++) acc[i][j] = 0.0f;

    // preload first k-tile into registers
    float a_reg[4], b_reg[4];
#pragma unroll
    for (int i = 0; i < 4; i++) {
        a_reg[i] = A[(size_t)(m0 + lr[i]) * II + lc[i]];
        b_reg[i] = W[(size_t)(n0 + lr[i]) * II + lc[i]];
    }

    for (int kt = 0; kt < II; kt += 16) {
#pragma unroll
        for (int i = 0; i < 4; i++) {
            As[lc[i]][lr[i]] = a_reg[i];
            Bs[lc[i]][lr[i]] = b_reg[i];
        }
        __syncthreads();

        if (kt + 16 < II) {
#pragma unroll
            for (int i = 0; i < 4; i++) {
                a_reg[i] = A[(size_t)(m0 + lr[i]) * II + (kt + 16) + lc[i]];
                b_reg[i] = W[(size_t)(n0 + lr[i]) * II + (kt + 16) + lc[i]];
            }
        }

#pragma unroll
        for (int k = 0; k < 16; k++) {
            float4 a4 = *(const float4*)&As[k][ty * 4];
            float4 b4 = *(const float4*)&Bs[k][tx * 4];
            float av[4] = {a4.x, a4.y, a4.z, a4.w};
            float bv[4] = {b4.x, b4.y, b4.z, b4.w};
#pragma unroll
            for (int i = 0; i < 4; i++)
#pragma unroll
                for (int j = 0; j < 4; j++)
                    acc[i][j] += av[i] * bv[j];
        }
        __syncthreads();
    }

    // scatter: m = t*BB + b ; m0 is a multiple of 64 == BB, so t is constant/CTA
    const int t = m0 / BB;
#pragma unroll
    for (int i = 0; i < 4; i++) {
        int b = ty * 4 + i;
        size_t base = (size_t)b * (TT * DD) + (size_t)t * DD;
#pragma unroll
        for (int j = 0; j < 4; j++) {
            int n = n0 + tx * 4 + j;
            out[base + n] = acc[i][j] + bias[n];
        }
    }
}

// ---------------------------------------------------------------------------
// Stage 2: persistent recurrence kernel.
// h_t = 0.5*h_{t-1} + 0.5*tanh(proj_t + h_{t-1} @ W_res^T)
// 128 CTAs; CTA c owns d-columns [16c, 16c+16) x all 64 batch rows.
// Grid barrier per step via per-step counters (zeroed by init each replay).
// proj_t read from out[b,t,d] then overwritten in-place with h_t.
// ---------------------------------------------------------------------------
__device__ __forceinline__ float fast_tanh(float x) {
    // 1 - 2/(e^{2x}+1): exact +/-1 at saturation (e^inf -> inf, e^-inf -> 0)
    float e = __expf(2.0f * x);
    return 1.0f - 2.0f / (e + 1.0f);
}

__global__ __launch_bounds__(256) void recur_kernel(
    const float* __restrict__ Wr,   // [DD, DD] row-major
    float* __restrict__ out)        // [BB, TT, DD]: holds proj, rewritten to h
{
    __shared__ float Hs[BB][S2_KT + 1];         // [b][k] 64x65 (conflict-free)
    __shared__ float Ws[S2_KT][S2_DTILE + 1];   // [k][d] 64x17

    const int tid = threadIdx.x;
    const int dd = tid & 15;        // d within tile
    const int bq = tid >> 4;        // batch quad 0..15
    const int d0 = blockIdx.x * S2_DTILE;
    const int d  = d0 + dd;

    // loader coords
    int hb[16], hk[16];
#pragma unroll
    for (int i = 0; i < 16; i++) {
        int idx = tid + i * 256;
        hb[i] = idx >> 6;           // 0..63
        hk[i] = idx & 63;
    }
    int wd[4], wk[4];
#pragma unroll
    for (int i = 0; i < 4; i++) {
        int idx = tid + i * 256;
        wd[i] = idx >> 6;           // 0..15
        wk[i] = idx & 63;
    }

    for (int t = 0; t < TT; t++) {
        const float* hin = g_h[t & 1];
        float* hout = g_h[(t + 1) & 1];

        float acc[4] = {0.0f, 0.0f, 0.0f, 0.0f};

        // prefetch chunk 0
        float h_reg[16], w_reg[4];
#pragma unroll
        for (int i = 0; i < 16; i++)
            h_reg[i] = __ldcg(&hin[hb[i] * DD + hk[i]]);
#pragma unroll
        for (int i = 0; i < 4; i++)
            w_reg[i] = Wr[(size_t)(d0 + wd[i]) * DD + wk[i]];

        for (int k0 = 0; k0 < DD; k0 += S2_KT) {
#pragma unroll
            for (int i = 0; i < 16; i++) Hs[hb[i]][hk[i]] = h_reg[i];
#pragma unroll
            for (int i = 0; i < 4; i++) Ws[wk[i]][wd[i]] = w_reg[i];
            __syncthreads();

            if (k0 + S2_KT < DD) {
                int kn = k0 + S2_KT;
#pragma unroll
                for (int i = 0; i < 16; i++)
                    h_reg[i] = __ldcg(&hin[hb[i] * DD + kn + hk[i]]);
#pragma unroll
                for (int i = 0; i < 4; i++)
                    w_reg[i] = Wr[(size_t)(d0 + wd[i]) * DD + kn + wk[i]];
            }

#pragma unroll
            for (int k = 0; k < S2_KT; k++) {
                float w = Ws[k][dd];
                acc[0] += Hs[bq * 4 + 0][k] * w;
                acc[1] += Hs[bq * 4 + 1][k] * w;
                acc[2] += Hs[bq * 4 + 2][k] * w;
                acc[3] += Hs[bq * 4 + 3][k] * w;
            }
            __syncthreads();
        }

        // epilogue: x = proj + hW ; h_new = 0.5 h + 0.5 tanh(x)
#pragma unroll
        for (int i = 0; i < 4; i++) {
            int b = bq * 4 + i;
            size_t oidx = (size_t)b * (TT * DD) + (size_t)t * DD + d;
            float x = out[oidx] + acc[i];
            float th = fast_tanh(x);
            float hprev = __ldcg(&hin[b * DD + d]);
            float hn = (1.0f - LEAK) * hprev + LEAK * th;
            hout[b * DD + d] = hn;
            out[oidx] = hn;
        }

        // grid-wide barrier (skip after the final step)
        if (t < TT - 1) {
            __threadfence();            // release: every thread's stores
            __syncthreads();
            if (tid == 0) {
                atomicAdd(&g_bar[t], 1u);
                volatile unsigned int* p = &g_bar[t];
                while (*p < (unsigned)S2_NCTA) { __nanosleep(64); }
            }
            __syncthreads();
        }
    }
}

// ---------------------------------------------------------------------------
// Launch
// ---------------------------------------------------------------------------
extern "C" void kernel_launch(void* const* d_in, const int* in_sizes, int n_in,
                              void* d_out, int out_size) {
    (void)in_sizes; (void)n_in; (void)out_size;
    const float* batch   = (const float*)d_in[0];  // [TT, BB, II]
    const float* input_w = (const float*)d_in[1];  // [DD, II]
    const float* res_w   = (const float*)d_in[2];  // [DD, DD]
    const float* bias    = (const float*)d_in[3];  // [DD]
    float* out = (float*)d_out;                    // [BB, TT, DD]

    init_kernel<<<64, 256>>>();

    dim3 g1(DD / 64, (TT * BB) / 64);   // 32 x 512
    proj_kernel<<<g1, 256>>>(batch, input_w, bias, out);

    recur_kernel<<<S2_NCTA, 256>>>(res_w, out);
}